// round 2
// baseline (speedup 1.0000x reference)
#include <cuda_runtime.h>

#define B_  32
#define T_  2048
#define IN_ 512
#define H_  256

// Scratch (allocation-free rule: __device__ globals)
__device__ float g_proj[(size_t)B_ * T_ * H_];   // 64 MB input projection
__device__ float g_Vt[H_ * H_];                  // V transposed: Vt[j][h] = V[h][j]

// ---------------------------------------------------------------------------
// Transpose V (tiny: 64K elements)
// ---------------------------------------------------------------------------
__global__ void transpose_V(const float* __restrict__ V) {
    int j = blockIdx.x;
    int h = threadIdx.x;
    g_Vt[j * H_ + h] = V[h * H_ + j];
}

// ---------------------------------------------------------------------------
// proj[m][n] = sum_k x[m][k] * W[n][k] + b[n]   (M=65536, N=256, K=512)
// reg-tiled fp32 SGEMM: block tile 128x64, BK=16, thread tile 8x4, 256 thr
// ---------------------------------------------------------------------------
#define BM 128
#define BN 64
#define BK 16
#define TM 8
#define TN 4

__global__ __launch_bounds__(256) void gemm_proj(
    const float* __restrict__ x, const float* __restrict__ W,
    const float* __restrict__ b) {
    __shared__ float As[BK][BM + 1];
    __shared__ float Bs[BK][BN + 1];
    const int bm = blockIdx.x * BM;
    const int bn = blockIdx.y * BN;
    const int tid = threadIdx.x;
    const int tx = tid & 15;        // -> N
    const int ty = tid >> 4;        // -> M
    float acc[TM][TN] = {};

    for (int k0 = 0; k0 < IN_; k0 += BK) {
        #pragma unroll
        for (int l = 0; l < (BM * BK) / 256; l++) {
            int e = l * 256 + tid;
            int i = e >> 4, j = e & 15;
            As[j][i] = x[(size_t)(bm + i) * IN_ + k0 + j];
        }
        #pragma unroll
        for (int l = 0; l < (BN * BK) / 256; l++) {
            int e = l * 256 + tid;
            int i = e >> 4, j = e & 15;
            Bs[j][i] = W[(size_t)(bn + i) * IN_ + k0 + j];
        }
        __syncthreads();
        #pragma unroll
        for (int kk = 0; kk < BK; kk++) {
            float a[TM], bb[TN];
            #pragma unroll
            for (int i = 0; i < TM; i++) a[i] = As[kk][ty * TM + i];
            #pragma unroll
            for (int j = 0; j < TN; j++) bb[j] = Bs[kk][tx * TN + j];
            #pragma unroll
            for (int i = 0; i < TM; i++)
                #pragma unroll
                for (int j = 0; j < TN; j++)
                    acc[i][j] = fmaf(a[i], bb[j], acc[i][j]);
        }
        __syncthreads();
    }
    #pragma unroll
    for (int i = 0; i < TM; i++) {
        int m = bm + ty * TM + i;
        #pragma unroll
        for (int j = 0; j < TN; j++) {
            int n = bn + tx * TN + j;
            g_proj[(size_t)m * H_ + n] = acc[i][j] + b[n];
        }
    }
}

// ---------------------------------------------------------------------------
// Sequential LIF scan. 1 CTA per batch, thread h owns neuron h.
// Spikes are binary -> rec = subset-sum over active rows of Vt.
// Active indices compacted into shared list each step (ballot + popc prefix).
// Double-buffered list -> 2 barriers per step.
// ---------------------------------------------------------------------------
__global__ __launch_bounds__(H_, 1) void scan_kernel(
    const float* __restrict__ b_rec, float* __restrict__ out) {
    const int b = blockIdx.x;
    const int h = threadIdx.x;
    const int wid = h >> 5, lane = h & 31;

    __shared__ unsigned sbits[2][8];
    __shared__ int slist[2][H_];

    const float* pb = g_proj + (size_t)b * T_ * H_;
    float* ob = out + (size_t)b * T_ * H_;

    const float brec = b_rec[h];
    float mem = 0.0f, spk_self = 0.0f;
    int cnt = 0, buf = 0;
    float p = pb[h];   // proj for t=0

    for (int t = 0; t < T_; t++) {
        // prefetch next step's projection (off critical path)
        float pn = (t + 1 < T_) ? pb[(size_t)(t + 1) * H_ + h] : 0.0f;

        // rec = sum of Vt rows for active presynaptic neurons (ascending j)
        float rec = 0.0f;
        const int* lst = slist[buf];
        int i = 0;
        for (; i + 4 <= cnt; i += 4) {
            float v0 = __ldg(&g_Vt[lst[i + 0] * H_ + h]);
            float v1 = __ldg(&g_Vt[lst[i + 1] * H_ + h]);
            float v2 = __ldg(&g_Vt[lst[i + 2] * H_ + h]);
            float v3 = __ldg(&g_Vt[lst[i + 3] * H_ + h]);
            rec = __fadd_rn(__fadd_rn(__fadd_rn(__fadd_rn(rec, v0), v1), v2), v3);
        }
        for (; i < cnt; i++)
            rec = __fadd_rn(rec, __ldg(&g_Vt[lst[i] * H_ + h]));
        rec = __fadd_rn(rec, brec);

        // LIF update (explicit rounding order, no FMA contraction surprises)
        float reset = (mem > 1.0f) ? 1.0f : 0.0f;
        float in_ = __fadd_rn(p, spk_self);
        mem = __fsub_rn(__fadd_rn(__fadd_rn(__fmul_rn(0.85f, mem), in_), rec), reset);
        float spk = (mem > 1.0f) ? 1.0f : 0.0f;
        ob[(size_t)t * H_ + h] = spk;

        // publish spikes: ballot -> bitmask -> compacted index list
        unsigned ball = __ballot_sync(0xFFFFFFFFu, spk != 0.0f);
        const int nb = buf ^ 1;
        if (lane == 0) sbits[nb][wid] = ball;
        __syncthreads();

        int base = 0, total = 0;
        #pragma unroll
        for (int w = 0; w < 8; w++) {
            int c = __popc(sbits[nb][w]);
            base += (w < wid) ? c : 0;
            total += c;
        }
        if (spk != 0.0f)
            slist[nb][base + __popc(ball & ((1u << lane) - 1u))] = h;
        __syncthreads();

        cnt = total;
        spk_self = spk;
        buf = nb;
        p = pn;
    }
}

// ---------------------------------------------------------------------------
extern "C" void kernel_launch(void* const* d_in, const int* in_sizes, int n_in,
                              void* d_out, int out_size) {
    const float* x     = (const float*)d_in[0];
    const float* W_in  = (const float*)d_in[1];
    const float* b_in  = (const float*)d_in[2];
    const float* V     = (const float*)d_in[3];
    const float* b_rec = (const float*)d_in[4];
    float* out = (float*)d_out;

    transpose_V<<<H_, H_>>>(V);
    gemm_proj<<<dim3((B_ * T_) / BM, H_ / BN), 256>>>(x, W_in, b_in);
    scan_kernel<<<B_, H_>>>(b_rec, out);
}

// round 3
// speedup vs baseline: 1.1894x; 1.1894x over previous
#include <cuda_runtime.h>

#define B_  32
#define T_  2048
#define IN_ 512
#define H_  256
#define JS  160          // Vt rows resident in shared memory (warps 0..4)

// Scratch (allocation-free rule: __device__ globals)
__device__ float g_proj[(size_t)B_ * T_ * H_];   // 64 MB input projection
__device__ float g_Vt[H_ * H_];                  // Vt[j][h] = V[h][j]

// ---------------------------------------------------------------------------
// Transpose V (tiny)
// ---------------------------------------------------------------------------
__global__ void transpose_V(const float* __restrict__ V) {
    int j = blockIdx.x;
    int h = threadIdx.x;
    g_Vt[j * H_ + h] = V[h * H_ + j];
}

// ---------------------------------------------------------------------------
// proj[m][n] = sum_k x[m][k]*W[n][k] + b[n]    M=65536 N=256 K=512
// 128x128x16 block tile, 8x8 thread tile, 256 threads, double-buffered smem
// ---------------------------------------------------------------------------
#define GBM 128
#define GBN 128
#define GBK 16

__global__ __launch_bounds__(256, 2) void gemm_proj(
    const float* __restrict__ x, const float* __restrict__ W,
    const float* __restrict__ bia) {
    __shared__ float As[2][GBK][GBM];
    __shared__ float Bs[2][GBK][GBN];
    const int bm = blockIdx.x * GBM;
    const int bn = blockIdx.y * GBN;
    const int tid = threadIdx.x;
    const int tx = tid & 15;    // -> n group (8 each)
    const int ty = tid >> 4;    // -> m group (8 each)
    const int lk = (tid & 3) * 4;   // float4 column within 16-wide k tile

    float acc[8][8];
    #pragma unroll
    for (int i = 0; i < 8; i++)
        #pragma unroll
        for (int j = 0; j < 8; j++) acc[i][j] = 0.0f;

    float4 ra[2], rb[2];

    // prologue: load k-tile 0
    #pragma unroll
    for (int it = 0; it < 2; it++) {
        int m = (it * 256 + tid) >> 2;
        ra[it] = *(const float4*)&x[(size_t)(bm + m) * IN_ + lk];
        rb[it] = *(const float4*)&W[(size_t)(bn + m) * IN_ + lk];
    }
    #pragma unroll
    for (int it = 0; it < 2; it++) {
        int m = (it * 256 + tid) >> 2;
        As[0][lk + 0][m] = ra[it].x; As[0][lk + 1][m] = ra[it].y;
        As[0][lk + 2][m] = ra[it].z; As[0][lk + 3][m] = ra[it].w;
        Bs[0][lk + 0][m] = rb[it].x; Bs[0][lk + 1][m] = rb[it].y;
        Bs[0][lk + 2][m] = rb[it].z; Bs[0][lk + 3][m] = rb[it].w;
    }
    __syncthreads();

    const int NT = IN_ / GBK;   // 32
    for (int kt = 0; kt < NT; kt++) {
        const int cur = kt & 1, nxt = cur ^ 1;
        if (kt + 1 < NT) {
            int k0 = (kt + 1) * GBK + lk;
            #pragma unroll
            for (int it = 0; it < 2; it++) {
                int m = (it * 256 + tid) >> 2;
                ra[it] = *(const float4*)&x[(size_t)(bm + m) * IN_ + k0];
                rb[it] = *(const float4*)&W[(size_t)(bn + m) * IN_ + k0];
            }
        }
        #pragma unroll
        for (int kk = 0; kk < GBK; kk++) {
            float a[8], bb[8];
            *(float4*)&a[0]  = *(const float4*)&As[cur][kk][ty * 8];
            *(float4*)&a[4]  = *(const float4*)&As[cur][kk][ty * 8 + 4];
            *(float4*)&bb[0] = *(const float4*)&Bs[cur][kk][tx * 8];
            *(float4*)&bb[4] = *(const float4*)&Bs[cur][kk][tx * 8 + 4];
            #pragma unroll
            for (int i = 0; i < 8; i++)
                #pragma unroll
                for (int j = 0; j < 8; j++)
                    acc[i][j] = fmaf(a[i], bb[j], acc[i][j]);
        }
        if (kt + 1 < NT) {
            #pragma unroll
            for (int it = 0; it < 2; it++) {
                int m = (it * 256 + tid) >> 2;
                As[nxt][lk + 0][m] = ra[it].x; As[nxt][lk + 1][m] = ra[it].y;
                As[nxt][lk + 2][m] = ra[it].z; As[nxt][lk + 3][m] = ra[it].w;
                Bs[nxt][lk + 0][m] = rb[it].x; Bs[nxt][lk + 1][m] = rb[it].y;
                Bs[nxt][lk + 2][m] = rb[it].z; Bs[nxt][lk + 3][m] = rb[it].w;
            }
        }
        __syncthreads();
    }

    // epilogue: add bias, write
    float bv[8];
    #pragma unroll
    for (int j = 0; j < 8; j++) bv[j] = bia[bn + tx * 8 + j];
    #pragma unroll
    for (int i = 0; i < 8; i++) {
        int m = bm + ty * 8 + i;
        float4 o0, o1;
        o0.x = acc[i][0] + bv[0]; o0.y = acc[i][1] + bv[1];
        o0.z = acc[i][2] + bv[2]; o0.w = acc[i][3] + bv[3];
        o1.x = acc[i][4] + bv[4]; o1.y = acc[i][5] + bv[5];
        o1.z = acc[i][6] + bv[6]; o1.w = acc[i][7] + bv[7];
        *(float4*)&g_proj[(size_t)m * H_ + bn + tx * 8]     = o0;
        *(float4*)&g_proj[(size_t)m * H_ + bn + tx * 8 + 4] = o1;
    }
}

// ---------------------------------------------------------------------------
// Sequential LIF scan. 1 CTA per batch, thread h = neuron h.
// Vt rows [0,JS) live in shared memory; rows [JS,256) via LDG (L1-resident).
// Active-spike index lists (byte offsets) compacted per step, double-buffered.
// 4-accumulator unrolled subset-sum.
// ---------------------------------------------------------------------------
__global__ __launch_bounds__(H_, 1) void scan_kernel(
    const float* __restrict__ b_rec, float* __restrict__ out) {
    extern __shared__ float sVt[];                 // [JS][H_]  160 KB
    __shared__ int slS[2][JS];                     // smem-part active list
    __shared__ int slG[2][H_ - JS];                // global-part active list
    __shared__ unsigned sbits[2][8];

    const int b = blockIdx.x;
    const int h = threadIdx.x;
    const int wid = h >> 5, lane = h & 31;

    // stage Vt[0..JS) into shared (coalesced float4 copy)
    {
        const float4* src = (const float4*)g_Vt;
        float4* dst = (float4*)sVt;
        #pragma unroll
        for (int i = 0; i < (JS * H_ / 4) / H_; i++)
            dst[i * H_ + h] = src[i * H_ + h];
    }
    __syncthreads();

    const char* sB = (const char*)sVt;
    const char* gB = (const char*)g_Vt;
    const float* pb = g_proj + (size_t)b * T_ * H_;
    float* ob = out + (size_t)b * T_ * H_;
    const float brec = b_rec[h];
    const int h4 = h * 4;

    float mem = 0.0f, spk = 0.0f;
    int cS = 0, cG = 0, buf = 0;
    float p0 = pb[h];
    float p1 = pb[H_ + h];

    for (int t = 0; t < T_; t++) {
        // prefetch proj two steps ahead (covers L2 latency)
        float p2 = (t + 2 < T_) ? pb[(size_t)(t + 2) * H_ + h] : 0.0f;

        float a0 = 0.0f, a1 = 0.0f, a2 = 0.0f, a3 = 0.0f;
        // shared-memory part (j < JS), ascending
        {
            const int* lS = slS[buf];
            int i = 0;
            for (; i + 4 <= cS; i += 4) {
                int4 o = *(const int4*)(lS + i);
                float v0 = *(const float*)(sB + o.x + h4);
                float v1 = *(const float*)(sB + o.y + h4);
                float v2 = *(const float*)(sB + o.z + h4);
                float v3 = *(const float*)(sB + o.w + h4);
                a0 += v0; a1 += v1; a2 += v2; a3 += v3;
            }
            for (; i < cS; i++)
                a0 += *(const float*)(sB + lS[i] + h4);
        }
        // global part (j >= JS), ascending
        {
            const int* lG = slG[buf];
            int i = 0;
            for (; i + 4 <= cG; i += 4) {
                int4 o = *(const int4*)(lG + i);
                float v0 = __ldg((const float*)(gB + o.x + h4));
                float v1 = __ldg((const float*)(gB + o.y + h4));
                float v2 = __ldg((const float*)(gB + o.z + h4));
                float v3 = __ldg((const float*)(gB + o.w + h4));
                a0 += v0; a1 += v1; a2 += v2; a3 += v3;
            }
            for (; i < cG; i++)
                a0 += __ldg((const float*)(gB + lG[i] + h4));
        }
        float rec = __fadd_rn(__fadd_rn(a0, a1), __fadd_rn(a2, a3));
        rec = __fadd_rn(rec, brec);

        // LIF update (explicit rounding order)
        float reset = (mem > 1.0f) ? 1.0f : 0.0f;
        float in_ = __fadd_rn(p0, spk);
        mem = __fsub_rn(__fadd_rn(__fadd_rn(__fmul_rn(0.85f, mem), in_), rec), reset);
        float s = (mem > 1.0f) ? 1.0f : 0.0f;
        ob[(size_t)t * H_ + h] = s;

        // publish: ballot -> per-group compaction (warps 0..4 -> S, 5..7 -> G)
        unsigned ball = __ballot_sync(0xFFFFFFFFu, s != 0.0f);
        const int nb = buf ^ 1;
        if (lane == 0) sbits[nb][wid] = ball;
        __syncthreads();

        int baseS = 0, totS = 0, baseG = 0, totG = 0;
        #pragma unroll
        for (int w = 0; w < 8; w++) {
            int c = __popc(sbits[nb][w]);
            if (w < 5) { totS += c; if (w < wid) baseS += c; }
            else       { totG += c; if (w < wid) baseG += c; }
        }
        if (s != 0.0f) {
            int rank = __popc(ball & ((1u << lane) - 1u));
            if (wid < 5) slS[nb][baseS + rank] = h << 10;   // byte offset j*1024
            else         slG[nb][baseG + rank] = h << 10;
        }
        __syncthreads();

        cS = totS; cG = totG; buf = nb; spk = s;
        p0 = p1; p1 = p2;
    }
}

// ---------------------------------------------------------------------------
extern "C" void kernel_launch(void* const* d_in, const int* in_sizes, int n_in,
                              void* d_out, int out_size) {
    const float* x     = (const float*)d_in[0];
    const float* W_in  = (const float*)d_in[1];
    const float* b_in  = (const float*)d_in[2];
    const float* V     = (const float*)d_in[3];
    const float* b_rec = (const float*)d_in[4];
    float* out = (float*)d_out;

    cudaFuncSetAttribute(scan_kernel,
                         cudaFuncAttributeMaxDynamicSharedMemorySize,
                         JS * H_ * sizeof(float));

    transpose_V<<<H_, H_>>>(V);
    gemm_proj<<<dim3((B_ * T_) / GBM, H_ / GBN), 256>>>(x, W_in, b_in);
    scan_kernel<<<B_, H_, JS * H_ * sizeof(float)>>>(b_rec, out);
}

// round 4
// speedup vs baseline: 2.5996x; 2.1857x over previous
#include <cuda_runtime.h>

#define B_  32
#define T_  2048
#define IN_ 512
#define H_  256
#define NG  32      // groups of 8 presynaptic neurons
#define NP  256     // patterns per group (2^8)

// Scratch (allocation-free rule: __device__ globals)
__device__ float g_proj[(size_t)B_ * T_ * H_];        // 64 MB input projection
__device__ float g_Vt[H_ * H_];                       // Vt[j][h] = V[h][j]
__device__ float g_tab[(size_t)NG * NP * H_];         // 8 MB group subset-sum table

// ---------------------------------------------------------------------------
// Transpose V (tiny)
// ---------------------------------------------------------------------------
__global__ void transpose_V(const float* __restrict__ V) {
    int j = blockIdx.x;
    int h = threadIdx.x;
    g_Vt[j * H_ + h] = V[h * H_ + j];
}

// ---------------------------------------------------------------------------
// Build subset-sum table: tab[g][p][h] = sum_{i: bit i of p} Vt[8g+i][h]
// (ascending i == ascending presynaptic index j)
// ---------------------------------------------------------------------------
__global__ void build_tab(void) {
    const int blk = blockIdx.x;          // 0..8191
    const int g = blk >> 8;
    const int p = blk & 255;
    const int h = threadIdx.x;
    float s = 0.0f;
    #pragma unroll
    for (int i = 0; i < 8; i++)
        if ((p >> i) & 1)
            s = __fadd_rn(s, g_Vt[(g * 8 + i) * H_ + h]);
    g_tab[((size_t)g * NP + p) * H_ + h] = s;
}

// ---------------------------------------------------------------------------
// proj[m][n] = sum_k x[m][k]*W[n][k] + b[n]    M=65536 N=256 K=512
// 128x128x16 block tile, 8x8 thread tile, 256 threads, double-buffered smem
// ---------------------------------------------------------------------------
#define GBM 128
#define GBN 128
#define GBK 16

__global__ __launch_bounds__(256, 2) void gemm_proj(
    const float* __restrict__ x, const float* __restrict__ W,
    const float* __restrict__ bia) {
    __shared__ float As[2][GBK][GBM];
    __shared__ float Bs[2][GBK][GBN];
    const int bm = blockIdx.x * GBM;
    const int bn = blockIdx.y * GBN;
    const int tid = threadIdx.x;
    const int tx = tid & 15;
    const int ty = tid >> 4;
    const int lk = (tid & 3) * 4;

    float acc[8][8];
    #pragma unroll
    for (int i = 0; i < 8; i++)
        #pragma unroll
        for (int j = 0; j < 8; j++) acc[i][j] = 0.0f;

    float4 ra[2], rb[2];

    #pragma unroll
    for (int it = 0; it < 2; it++) {
        int m = (it * 256 + tid) >> 2;
        ra[it] = *(const float4*)&x[(size_t)(bm + m) * IN_ + lk];
        rb[it] = *(const float4*)&W[(size_t)(bn + m) * IN_ + lk];
    }
    #pragma unroll
    for (int it = 0; it < 2; it++) {
        int m = (it * 256 + tid) >> 2;
        As[0][lk + 0][m] = ra[it].x; As[0][lk + 1][m] = ra[it].y;
        As[0][lk + 2][m] = ra[it].z; As[0][lk + 3][m] = ra[it].w;
        Bs[0][lk + 0][m] = rb[it].x; Bs[0][lk + 1][m] = rb[it].y;
        Bs[0][lk + 2][m] = rb[it].z; Bs[0][lk + 3][m] = rb[it].w;
    }
    __syncthreads();

    const int NT = IN_ / GBK;
    for (int kt = 0; kt < NT; kt++) {
        const int cur = kt & 1, nxt = cur ^ 1;
        if (kt + 1 < NT) {
            int k0 = (kt + 1) * GBK + lk;
            #pragma unroll
            for (int it = 0; it < 2; it++) {
                int m = (it * 256 + tid) >> 2;
                ra[it] = *(const float4*)&x[(size_t)(bm + m) * IN_ + k0];
                rb[it] = *(const float4*)&W[(size_t)(bn + m) * IN_ + k0];
            }
        }
        #pragma unroll
        for (int kk = 0; kk < GBK; kk++) {
            float a[8], bb[8];
            *(float4*)&a[0]  = *(const float4*)&As[cur][kk][ty * 8];
            *(float4*)&a[4]  = *(const float4*)&As[cur][kk][ty * 8 + 4];
            *(float4*)&bb[0] = *(const float4*)&Bs[cur][kk][tx * 8];
            *(float4*)&bb[4] = *(const float4*)&Bs[cur][kk][tx * 8 + 4];
            #pragma unroll
            for (int i = 0; i < 8; i++)
                #pragma unroll
                for (int j = 0; j < 8; j++)
                    acc[i][j] = fmaf(a[i], bb[j], acc[i][j]);
        }
        if (kt + 1 < NT) {
            #pragma unroll
            for (int it = 0; it < 2; it++) {
                int m = (it * 256 + tid) >> 2;
                As[nxt][lk + 0][m] = ra[it].x; As[nxt][lk + 1][m] = ra[it].y;
                As[nxt][lk + 2][m] = ra[it].z; As[nxt][lk + 3][m] = ra[it].w;
                Bs[nxt][lk + 0][m] = rb[it].x; Bs[nxt][lk + 1][m] = rb[it].y;
                Bs[nxt][lk + 2][m] = rb[it].z; Bs[nxt][lk + 3][m] = rb[it].w;
            }
        }
        __syncthreads();
    }

    float bv[8];
    #pragma unroll
    for (int j = 0; j < 8; j++) bv[j] = bia[bn + tx * 8 + j];
    #pragma unroll
    for (int i = 0; i < 8; i++) {
        int m = bm + ty * 8 + i;
        float4 o0, o1;
        o0.x = acc[i][0] + bv[0]; o0.y = acc[i][1] + bv[1];
        o0.z = acc[i][2] + bv[2]; o0.w = acc[i][3] + bv[3];
        o1.x = acc[i][4] + bv[4]; o1.y = acc[i][5] + bv[5];
        o1.z = acc[i][6] + bv[6]; o1.w = acc[i][7] + bv[7];
        *(float4*)&g_proj[(size_t)m * H_ + bn + tx * 8]     = o0;
        *(float4*)&g_proj[(size_t)m * H_ + bn + tx * 8 + 4] = o1;
    }
}

// ---------------------------------------------------------------------------
// Sequential LIF scan with group-table lookups.
// 1 CTA per batch (256 threads). Thread layout for rec phase:
//   quarter q = tid>>6 (handles groups 8q..8q+7), u = tid&63 (h-quad u*4..u*4+3)
//   Each thread: 8 x LDG.128 from g_tab (pattern-indexed rows) -> float4 acc.
// Combine 4 quarter-partials per neuron, then LIF update by thread h = tid.
// Spike mask published via ballot words only (no list compaction).
// ---------------------------------------------------------------------------
__global__ __launch_bounds__(H_, 1) void scan_kernel(
    const float* __restrict__ b_rec, float* __restrict__ out) {
    __shared__ float4 sp[2][4][64];        // quarter partial sums
    __shared__ unsigned sbits[2][8];       // spike ballot words

    const int b = blockIdx.x;
    const int tid = threadIdx.x;
    const int h = tid;
    const int wid = tid >> 5, lane = tid & 31;
    const int q = tid >> 6, u = tid & 63;

    const float* pb = g_proj + (size_t)b * T_ * H_;
    float* ob = out + (size_t)b * T_ * H_;
    const float brec = b_rec[h];

    // per-thread base into the table for this quarter's groups, at h-quad u
    const char* tbase = (const char*)g_tab
                      + ((size_t)q * 8 * NP * H_ * 4)   // group block
                      + (size_t)u * 16;                  // h-quad offset

    if (tid < 8) sbits[0][tid] = 0u;
    __syncthreads();

    float mem = 0.0f, spk = 0.0f;
    int buf = 0;
    float p0 = pb[h];
    float p1 = pb[H_ + h];

    for (int t = 0; t < T_; t++) {
        float p2 = (t + 2 < T_) ? pb[(size_t)(t + 2) * H_ + h] : 0.0f;

        // ---- phase 1: table-row gather (groups ascending = j ascending) ----
        const unsigned wA = sbits[buf][2 * q];
        const unsigned wB = sbits[buf][2 * q + 1];
        float4 acc = make_float4(0.f, 0.f, 0.f, 0.f);
        #pragma unroll
        for (int i = 0; i < 8; i++) {
            unsigned pat = (i < 4) ? ((wA >> (8 * i)) & 0xFFu)
                                   : ((wB >> (8 * (i - 4))) & 0xFFu);
            // row byte offset within quarter block: (i*256 + pat) * 1024
            const float4 v = *(const float4*)(tbase + (((unsigned)i << 8) + pat) * 1024u);
            acc.x = __fadd_rn(acc.x, v.x);
            acc.y = __fadd_rn(acc.y, v.y);
            acc.z = __fadd_rn(acc.z, v.z);
            acc.w = __fadd_rn(acc.w, v.w);
        }
        sp[buf][q][u] = acc;
        __syncthreads();   // A

        // ---- phase 2: combine quarters + LIF update (thread h = neuron h) ----
        const int uu = h >> 2, c = h & 3;
        const float r0 = ((const float*)&sp[buf][0][uu])[c];
        const float r1 = ((const float*)&sp[buf][1][uu])[c];
        const float r2 = ((const float*)&sp[buf][2][uu])[c];
        const float r3 = ((const float*)&sp[buf][3][uu])[c];
        float rec = __fadd_rn(__fadd_rn(r0, r1), __fadd_rn(r2, r3));
        rec = __fadd_rn(rec, brec);

        const float reset = (mem > 1.0f) ? 1.0f : 0.0f;
        const float in_ = __fadd_rn(p0, spk);
        mem = __fsub_rn(__fadd_rn(__fadd_rn(__fmul_rn(0.85f, mem), in_), rec), reset);
        const float s = (mem > 1.0f) ? 1.0f : 0.0f;
        ob[(size_t)t * H_ + h] = s;

        const unsigned ball = __ballot_sync(0xFFFFFFFFu, s != 0.0f);
        const int nb = buf ^ 1;
        if (lane == 0) sbits[nb][wid] = ball;
        __syncthreads();   // B

        buf = nb; spk = s;
        p0 = p1; p1 = p2;
    }
}

// ---------------------------------------------------------------------------
extern "C" void kernel_launch(void* const* d_in, const int* in_sizes, int n_in,
                              void* d_out, int out_size) {
    const float* x     = (const float*)d_in[0];
    const float* W_in  = (const float*)d_in[1];
    const float* b_in  = (const float*)d_in[2];
    const float* V     = (const float*)d_in[3];
    const float* b_rec = (const float*)d_in[4];
    float* out = (float*)d_out;

    transpose_V<<<H_, H_>>>(V);
    build_tab<<<NG * NP, H_>>>();
    gemm_proj<<<dim3((B_ * T_) / GBM, H_ / GBN), 256>>>(x, W_in, b_in);
    scan_kernel<<<B_, H_>>>(b_rec, out);
}